// round 2
// baseline (speedup 1.0000x reference)
#include <cuda_runtime.h>
#include <cstddef>

#define N_MAX 50000
#define FIN   256
#define FOUT  128

// ---------------------------------------------------------------------------
// Scratch (static device globals — no runtime allocation allowed)
// ---------------------------------------------------------------------------
__device__ float g_m[(size_t)N_MAX * FOUT];   // per-node mean message  m = relu(xWm)*att*n1
__device__ float g_v[(size_t)N_MAX * FOUT];   // per-node var  message  v = relu(xWv)*att^2*n1^2
__device__ float g_degs[N_MAX];
__device__ float g_norm1[N_MAX];

// ---------------------------------------------------------------------------
// Degree / norm kernels
// ---------------------------------------------------------------------------
__global__ void deg_kernel(const int* __restrict__ dst, int E) {
    for (int i = blockIdx.x * blockDim.x + threadIdx.x; i < E;
         i += gridDim.x * blockDim.x)
        atomicAdd(&g_degs[dst[i]], 1.0f);
}

__global__ void norm_kernel(int n) {
    int i = blockIdx.x * blockDim.x + threadIdx.x;
    if (i < n) {
        float d = g_degs[i];
        d = (d < 1.0f) ? 1.0f : d;
        g_norm1[i] = rsqrtf(d);
    }
}

// ---------------------------------------------------------------------------
// Fused dual-GEMM + message epilogue.
// C tile: 64 rows x 128 cols (full FOUT), both W matrices in one pass so the
// elementwise coupling (att = exp(-var) scales both mean and var messages)
// stays in registers. 256 threads, 4x8 microtile per thread per matrix.
// ---------------------------------------------------------------------------
__global__ void __launch_bounds__(256, 2) gemm_msg_kernel(
    const float* __restrict__ feat,
    const float* __restrict__ Wm,
    const float* __restrict__ Wv,
    int n)
{
    __shared__ float sA[16][64];      // feat tile, stored [k][m]
    __shared__ float sWm[16][FOUT];   // [k][n]
    __shared__ float sWv[16][FOUT];

    const int t  = threadIdx.x;
    const int m0 = blockIdx.x * 64;
    const int tm = t >> 4;            // 0..15 -> m group
    const int tn = t & 15;            // 0..15 -> n group

    float accM[4][8];
    float accV[4][8];
#pragma unroll
    for (int i = 0; i < 4; i++)
#pragma unroll
        for (int j = 0; j < 8; j++) { accM[i][j] = 0.0f; accV[i][j] = 0.0f; }

    const int  arow = t >> 2;          // 0..63
    const int  ac4  = (t & 3) * 4;     // 0,4,8,12
    const int  wr   = t >> 5;          // 0..7
    const int  wc   = (t & 31) * 4;    // 0..124
    const bool aok  = (m0 + arow) < n;
    const float* aptr = feat + (size_t)(m0 + arow) * FIN + ac4;

    for (int kb = 0; kb < FIN; kb += 16) {
        float4 av = make_float4(0.0f, 0.0f, 0.0f, 0.0f);
        if (aok) av = *(const float4*)(aptr + kb);
        sA[ac4 + 0][arow] = av.x;
        sA[ac4 + 1][arow] = av.y;
        sA[ac4 + 2][arow] = av.z;
        sA[ac4 + 3][arow] = av.w;

        *(float4*)&sWm[wr][wc]     = *(const float4*)(Wm + (size_t)(kb + wr)     * FOUT + wc);
        *(float4*)&sWm[wr + 8][wc] = *(const float4*)(Wm + (size_t)(kb + wr + 8) * FOUT + wc);
        *(float4*)&sWv[wr][wc]     = *(const float4*)(Wv + (size_t)(kb + wr)     * FOUT + wc);
        *(float4*)&sWv[wr + 8][wc] = *(const float4*)(Wv + (size_t)(kb + wr + 8) * FOUT + wc);

        __syncthreads();

#pragma unroll
        for (int k = 0; k < 16; k++) {
            float4 a4 = *(const float4*)&sA[k][tm * 4];
            float4 b0 = *(const float4*)&sWm[k][tn * 8];
            float4 b1 = *(const float4*)&sWm[k][tn * 8 + 4];
            float4 c0 = *(const float4*)&sWv[k][tn * 8];
            float4 c1 = *(const float4*)&sWv[k][tn * 8 + 4];
            float aa[4] = {a4.x, a4.y, a4.z, a4.w};
            float bb[8] = {b0.x, b0.y, b0.z, b0.w, b1.x, b1.y, b1.z, b1.w};
            float cc[8] = {c0.x, c0.y, c0.z, c0.w, c1.x, c1.y, c1.z, c1.w};
#pragma unroll
            for (int i = 0; i < 4; i++)
#pragma unroll
                for (int j = 0; j < 8; j++) {
                    accM[i][j] = fmaf(aa[i], bb[j], accM[i][j]);
                    accV[i][j] = fmaf(aa[i], cc[j], accV[i][j]);
                }
        }
        __syncthreads();
    }

    // Epilogue: relu, attention, degree norm -> per-node messages
#pragma unroll
    for (int i = 0; i < 4; i++) {
        int node = m0 + tm * 4 + i;
        if (node >= n) continue;
        float n1 = g_norm1[node];
        float n2 = n1 * n1;
        float mo[8], vo[8];
#pragma unroll
        for (int j = 0; j < 8; j++) {
            float mean = fmaxf(accM[i][j], 0.0f);
            float var  = fmaxf(accV[i][j], 0.0f);
            float att  = __expf(-var);          // GAMMA = 1.0
            mo[j] = mean * att * n1;
            vo[j] = var * att * att * n2;
        }
        float* pm = g_m + (size_t)node * FOUT + tn * 8;
        float* pv = g_v + (size_t)node * FOUT + tn * 8;
        *(float4*)(pm)     = make_float4(mo[0], mo[1], mo[2], mo[3]);
        *(float4*)(pm + 4) = make_float4(mo[4], mo[5], mo[6], mo[7]);
        *(float4*)(pv)     = make_float4(vo[0], vo[1], vo[2], vo[3]);
        *(float4*)(pv + 4) = make_float4(vo[4], vo[5], vo[6], vo[7]);
    }
}

// ---------------------------------------------------------------------------
// Edge aggregation: one warp per edge; each lane moves one float4 of the
// 128-float row, scatter-added with red.global.add.v4.f32 (no return value,
// 4 floats per LSU lane-op). Indices loaded once by lane 0 and broadcast.
// ---------------------------------------------------------------------------
__device__ __forceinline__ void red_add_v4(float* addr, float4 v) {
    asm volatile("red.global.add.v4.f32 [%0], {%1, %2, %3, %4};"
                 :: "l"(addr), "f"(v.x), "f"(v.y), "f"(v.z), "f"(v.w)
                 : "memory");
}

__global__ void agg_kernel(const int* __restrict__ src,
                           const int* __restrict__ dst,
                           float* __restrict__ out_mean,
                           float* __restrict__ out_var,
                           int E)
{
    int warp = (int)((blockIdx.x * (size_t)blockDim.x + threadIdx.x) >> 5);
    int lane = threadIdx.x & 31;
    if (warp >= E) return;

    int s = 0, d = 0;
    if (lane == 0) {
        s = __ldg(src + warp);
        d = __ldg(dst + warp);
    }
    s = __shfl_sync(0xFFFFFFFFu, s, 0);
    d = __shfl_sync(0xFFFFFFFFu, d, 0);

    float4 a = *(const float4*)(g_m + (size_t)s * FOUT + lane * 4);
    float4 b = *(const float4*)(g_v + (size_t)s * FOUT + lane * 4);

    red_add_v4(out_mean + (size_t)d * FOUT + lane * 4, a);
    red_add_v4(out_var  + (size_t)d * FOUT + lane * 4, b);
}

// ---------------------------------------------------------------------------
// Final norm scale: mean_out *= n1[dst], var_out *= n1[dst]^2 (in place)
// ---------------------------------------------------------------------------
__global__ void scale_kernel(float* __restrict__ out, int n) {
    int i = blockIdx.x * blockDim.x + threadIdx.x;  // one float4 per thread
    int total = n * (FOUT / 4);
    if (i >= total) return;
    int node = i / (FOUT / 4);
    float n1 = g_norm1[node];
    float n2 = n1 * n1;
    float4* pm = (float4*)out + i;
    float4* pv = (float4*)out + total + i;
    float4 m = *pm;
    float4 v = *pv;
    m.x *= n1; m.y *= n1; m.z *= n1; m.w *= n1;
    v.x *= n2; v.y *= n2; v.z *= n2; v.w *= n2;
    *pm = m;
    *pv = v;
}

// ---------------------------------------------------------------------------
// Launch
// ---------------------------------------------------------------------------
extern "C" void kernel_launch(void* const* d_in, const int* in_sizes, int n_in,
                              void* d_out, int out_size)
{
    const float* feat = (const float*)d_in[0];
    const int*   esrc = (const int*)d_in[1];
    const int*   edst = (const int*)d_in[2];
    const float* Wm   = (const float*)d_in[3];
    const float* Wv   = (const float*)d_in[4];
    float* out = (float*)d_out;

    int n = in_sizes[0] / FIN;   // 50000
    int E = in_sizes[1];         // 800000

    float* out_mean = out;
    float* out_var  = out + (size_t)n * FOUT;

    // Zero output accumulators and degree counters (async, capturable).
    cudaMemsetAsync(d_out, 0, (size_t)out_size * sizeof(float));
    void* degs_ptr = nullptr;
    cudaGetSymbolAddress(&degs_ptr, g_degs);
    cudaMemsetAsync(degs_ptr, 0, (size_t)N_MAX * sizeof(float));

    deg_kernel<<<592, 256>>>(edst, E);           // grid-stride, ~4 waves
    norm_kernel<<<(n + 255) / 256, 256>>>(n);

    gemm_msg_kernel<<<(n + 63) / 64, 256>>>(feat, Wm, Wv, n);

    long long agg_threads = (long long)E * 32;
    agg_kernel<<<(unsigned)((agg_threads + 255) / 256), 256>>>(esrc, edst, out_mean, out_var, E);

    scale_kernel<<<(n * (FOUT / 4) + 255) / 256, 256>>>(out, n);
}